// round 16
// baseline (speedup 1.0000x reference)
#include <cuda_runtime.h>
#include <cuda_bf16.h>
#include <math.h>
#include <stdint.h>

#define DIM   1024
#define T_TOK 16384
#define NL    3
#define NEXP  4
#define RRANK 16
#define LN_EPS 1e-5f

#define T2 (2 * T_TOK)     // both stacks batched

// ---------------- scratch (no allocations allowed) ----------------
__device__ float g_bufY[(size_t)T2 * DIM];               // pre-LN Y (fp32), batched
__device__ float g_bufA[(size_t)T2 * DIM];               // post-LN activation, batched
__device__ __nv_bfloat16 g_Zhi[(size_t)T2 * DIM];        // gemm<0> A operand split
__device__ __nv_bfloat16 g_Zlo[(size_t)T2 * DIM];
__device__ __nv_bfloat16 g_Shi[(size_t)T2 * DIM];        // liquid state S split
__device__ __nv_bfloat16 g_Slo[(size_t)T2 * DIM];
// 12 weight slots: slot = stk*6 + l*2 + which(0=Wi,1=Wo); each W^T [N][K]
__device__ __nv_bfloat16 g_WhiAll[(size_t)12 * DIM * DIM];
__device__ __nv_bfloat16 g_WloAll[(size_t)12 * DIM * DIM];

// ================= PTX helpers (base compute_103 only) =================
__device__ __forceinline__ uint32_t smem_u32(const void* p) {
    uint32_t a;
    asm("{ .reg .u64 t; cvta.to.shared.u64 t, %1; cvt.u32.u64 %0, t; }" : "=r"(a) : "l"(p));
    return a;
}

__device__ __forceinline__ void cp_async16(uint32_t dst, const void* src) {
    asm volatile("cp.async.cg.shared.global [%0], [%1], 16;" :: "r"(dst), "l"(src));
}
#define CP_COMMIT() asm volatile("cp.async.commit_group;" ::: "memory")
#define CP_WAIT0()  asm volatile("cp.async.wait_group 0;" ::: "memory")
#define CP_WAIT1()  asm volatile("cp.async.wait_group 1;" ::: "memory")

__device__ __forceinline__ void ldsm_x4(uint32_t* r, uint32_t addr) {
    asm volatile("ldmatrix.sync.aligned.m8n8.x4.shared.b16 {%0,%1,%2,%3}, [%4];"
                 : "=r"(r[0]), "=r"(r[1]), "=r"(r[2]), "=r"(r[3]) : "r"(addr));
}

__device__ __forceinline__ void mma_bf16(float* d, const uint32_t* a, const uint32_t* b) {
    asm volatile(
        "mma.sync.aligned.m16n8k16.row.col.f32.bf16.bf16.f32 "
        "{%0,%1,%2,%3}, {%4,%5,%6,%7}, {%8,%9}, {%0,%1,%2,%3};"
        : "+f"(d[0]), "+f"(d[1]), "+f"(d[2]), "+f"(d[3])
        : "r"(a[0]), "r"(a[1]), "r"(a[2]), "r"(a[3]), "r"(b[0]), "r"(b[1]));
}

// split a float4 into packed-4 hi bf16 and packed-4 lo bf16 (8 bytes each)
__device__ __forceinline__ void split4(float4 v, unsigned long long& hi, unsigned long long& lo) {
    __nv_bfloat162 h0 = __float22bfloat162_rn(make_float2(v.x, v.y));
    __nv_bfloat162 h1 = __float22bfloat162_rn(make_float2(v.z, v.w));
    float2 f0 = __bfloat1622float2(h0);
    float2 f1 = __bfloat1622float2(h1);
    __nv_bfloat162 l0 = __float22bfloat162_rn(make_float2(v.x - f0.x, v.y - f0.y));
    __nv_bfloat162 l1 = __float22bfloat162_rn(make_float2(v.z - f1.x, v.w - f1.y));
    uint32_t uh0 = *reinterpret_cast<uint32_t*>(&h0);
    uint32_t uh1 = *reinterpret_cast<uint32_t*>(&h1);
    uint32_t ul0 = *reinterpret_cast<uint32_t*>(&l0);
    uint32_t ul1 = *reinterpret_cast<uint32_t*>(&l1);
    hi = (unsigned long long)uh0 | ((unsigned long long)uh1 << 32);
    lo = (unsigned long long)ul0 | ((unsigned long long)ul1 << 32);
}

__device__ __forceinline__ void split2(float a, float b, uint32_t& hi, uint32_t& lo) {
    __nv_bfloat162 h = __float22bfloat162_rn(make_float2(a, b));
    float2 f = __bfloat1622float2(h);
    __nv_bfloat162 l = __float22bfloat162_rn(make_float2(a - f.x, b - f.y));
    hi = *reinterpret_cast<uint32_t*>(&h);
    lo = *reinterpret_cast<uint32_t*>(&l);
}

// ---------------- x split: both stacks in one launch (z = stack) ----------------
__global__ __launch_bounds__(256)
void xsplit_kernel(const float* __restrict__ XE, const float* __restrict__ XT,
                   __nv_bfloat16* __restrict__ Xhi, __nv_bfloat16* __restrict__ Xlo)
{
    const int stk = blockIdx.y;
    const float* X = stk ? XT : XE;
    const size_t idx = (size_t)blockIdx.x * 256 + threadIdx.x;               // float4 idx
    const size_t gout = (size_t)stk * (T_TOK * DIM / 4) + idx;
    float4 v = ((const float4*)X)[idx];
    unsigned long long hi, lo;
    split4(v, hi, lo);
    ((unsigned long long*)Xhi)[gout] = hi;
    ((unsigned long long*)Xlo)[gout] = lo;
}

// ---------------- all 12 weight transpose+splits in ONE launch ----------------
__global__ __launch_bounds__(256)
void wsplit_all_kernel(const float* __restrict__ encWi, const float* __restrict__ encWo,
                       const float* __restrict__ tgtWi, const float* __restrict__ tgtWo,
                       __nv_bfloat16* __restrict__ WhiAll, __nv_bfloat16* __restrict__ WloAll)
{
    __shared__ float tile[32][33];
    const int s = blockIdx.z;
    const int stk = s / 6, rem = s % 6, l = rem >> 1, which = rem & 1;
    const float* Wbase = stk ? (which ? tgtWo : tgtWi) : (which ? encWo : encWi);
    const float* W = Wbase + (size_t)l * DIM * DIM;
    __nv_bfloat16* Whi = WhiAll + (size_t)s * DIM * DIM;
    __nv_bfloat16* Wlo = WloAll + (size_t)s * DIM * DIM;

    const int n0 = blockIdx.x * 32, k0 = blockIdx.y * 32;
    const int tx = threadIdx.x & 31, ty = threadIdx.x >> 5;
#pragma unroll
    for (int i = 0; i < 32; i += 8)
        tile[ty + i][tx] = W[(size_t)(k0 + ty + i) * DIM + n0 + tx];
    __syncthreads();
#pragma unroll
    for (int i = 0; i < 32; i += 8) {
        float v = tile[tx][ty + i];             // W[k0+tx][n0+ty+i]
        __nv_bfloat16 h = __float2bfloat16(v);
        const size_t o = (size_t)(n0 + ty + i) * DIM + k0 + tx;
        Whi[o] = h;
        Wlo[o] = __float2bfloat16(v - __bfloat162float(h));
    }
}

// ---------------- HMMA bf16x3 GEMM: 4 warps, 64x64 warp tiles ----------------
// MODE 0: s = sigmoid(acc + bias[c]) * cur[r,c] * td[c]  -> split bf16 (outHi/outLo, batched)
// MODE 1: out = acc + bias[c] + cur[r,c]                 -> fp32 (outF, batched)
// CTA tile 128x128, 128 threads (2M x 2N warps), BK=32, 3-stage cp.async pipeline.
// stage (32KB): Ah[128][32] @0, Al @8192, Bh[128n][32k] @16384, Bl @24576
// layout: byteoff(row, q16B) = row*64 + ((q ^ (row&3))<<4)
#define BKC      32
#define NCH      (DIM / BKC)     // 32
#define STAGE_B  32768
#define NSTAGE   3
#define SMEMSZ   (NSTAGE * STAGE_B)

template <int MODE>
__global__ __launch_bounds__(128, 2)
void gemm_mma(const __nv_bfloat16* __restrict__ Ahi, const __nv_bfloat16* __restrict__ Alo,
              const __nv_bfloat16* __restrict__ WhiAll, const __nv_bfloat16* __restrict__ WloAll,
              int wslot,
              const float* __restrict__ biasE, const float* __restrict__ biasT,
              const float* __restrict__ curE, const float* __restrict__ curT,
              const float* __restrict__ tdE, const float* __restrict__ tdT,
              float* __restrict__ outF,
              __nv_bfloat16* __restrict__ outHi, __nv_bfloat16* __restrict__ outLo)
{
    extern __shared__ char smem[];
    const uint32_t sb = smem_u32(smem);
    const int tid  = threadIdx.x;
    const int wid  = tid >> 5, lane = tid & 31;
    const int mTile = blockIdx.y, nTile = blockIdx.x;
    const int stk = blockIdx.z;
    const int wm = wid >> 1;      // 0..1
    const int wn = wid & 1;       // 0..1

    const size_t rowBaseG = (size_t)stk * T_TOK + (size_t)mTile * 128;
    const __nv_bfloat16* AhG = Ahi + rowBaseG * DIM;
    const __nv_bfloat16* AlG = Alo + rowBaseG * DIM;
    const size_t wOff = ((size_t)(wslot + stk * 6)) * DIM * DIM + (size_t)nTile * 128 * DIM;
    const __nv_bfloat16* BhG = WhiAll + wOff;
    const __nv_bfloat16* BlG = WloAll + wOff;

    const float* bias = stk ? biasT : biasE;
    const float* cur  = stk ? curT  : curE;     // indexed by LOCAL row
    const float* td   = stk ? tdT   : tdE;

    const int fR = tid >> 2;      // 0..31
    const int fQ = tid & 3;       // 16B chunk within 64B row

    // acc[mt][bt][half][4]: warp tile 64x64 = 4 mt x 4 bt x 2 (8-col) halves
    float acc[4][4][2][4];
#pragma unroll
    for (int mt = 0; mt < 4; ++mt)
#pragma unroll
        for (int bt = 0; bt < 4; ++bt)
#pragma unroll
            for (int h = 0; h < 2; ++h)
#pragma unroll
                for (int r = 0; r < 4; ++r) acc[mt][bt][h][r] = 0.f;

    auto fillStage = [&](int st, int k0) {
        const uint32_t base = sb + st * STAGE_B;
#pragma unroll
        for (int i = 0; i < 4; ++i) {
            const int r = fR + i * 32;
            const uint32_t off = (uint32_t)(r * 64 + ((fQ ^ (r & 3)) << 4));
            const size_t go = (size_t)r * DIM + k0 + fQ * 8;
            cp_async16(base + off,         AhG + go);
            cp_async16(base + 8192 + off,  AlG + go);
            cp_async16(base + 16384 + off, BhG + go);
            cp_async16(base + 24576 + off, BlG + go);
        }
        CP_COMMIT();
    };

    fillStage(0, 0);
    fillStage(1, BKC);

    const int l7 = lane & 7, l8 = (lane >> 3) & 1, l16 = lane >> 4;

    for (int c = 0; c < NCH; ++c) {
        if (c + 1 < NCH) { CP_WAIT1(); } else { CP_WAIT0(); }
        __syncthreads();
        // stage (c+2)%3 was last read during chunk c-1; all warps have finished
        // those ldsm (program order before this barrier), so refill is safe.
        if (c + 2 < NCH) fillStage((c + 2) % NSTAGE, (c + 2) * BKC);

        const uint32_t sA = sb + (c % NSTAGE) * STAGE_B;
        const uint32_t sB = sA + 16384;
#pragma unroll
        for (int ks = 0; ks < 2; ++ks) {
            uint32_t b_hi[4][4], b_lo[4][4];
#pragma unroll
            for (int bt = 0; bt < 4; ++bt) {
                const int n = wn * 64 + bt * 16 + l16 * 8 + l7;
                const int ch = (ks * 2 + l8) ^ (n & 3);
                const uint32_t off = (uint32_t)(n * 64 + (ch << 4));
                ldsm_x4(b_hi[bt], sB + off);
                ldsm_x4(b_lo[bt], sB + 8192 + off);
            }
#pragma unroll
            for (int mt = 0; mt < 4; ++mt) {
                uint32_t a_hi[4], a_lo[4];
                const int r = wm * 64 + mt * 16 + l8 * 8 + l7;
                const int ch = (ks * 2 + l16) ^ (r & 3);
                const uint32_t off = (uint32_t)(r * 64 + (ch << 4));
                ldsm_x4(a_hi, sA + off);
                ldsm_x4(a_lo, sA + 8192 + off);
#pragma unroll
                for (int bt = 0; bt < 4; ++bt) {
                    mma_bf16(acc[mt][bt][0], a_hi, &b_hi[bt][0]);
                    mma_bf16(acc[mt][bt][0], a_hi, &b_lo[bt][0]);
                    mma_bf16(acc[mt][bt][0], a_lo, &b_hi[bt][0]);
                    mma_bf16(acc[mt][bt][1], a_hi, &b_hi[bt][2]);
                    mma_bf16(acc[mt][bt][1], a_hi, &b_lo[bt][2]);
                    mma_bf16(acc[mt][bt][1], a_lo, &b_hi[bt][2]);
                }
            }
        }
    }

    // ---- epilogue ----
    const int rq = lane >> 2;
    const int cq = (lane & 3) * 2;
#pragma unroll
    for (int mt = 0; mt < 4; ++mt) {
#pragma unroll
        for (int h = 0; h < 2; ++h) {
            const int lrow = mTile * 128 + wm * 64 + mt * 16 + h * 8 + rq;
            const size_t grow = (size_t)stk * T_TOK + lrow;
            const float* curRow = cur + (size_t)lrow * DIM;
#pragma unroll
            for (int bt = 0; bt < 4; ++bt) {
#pragma unroll
                for (int half = 0; half < 2; ++half) {
                    const int col = nTile * 128 + wn * 64 + bt * 16 + half * 8 + cq;
                    float v0 = acc[mt][bt][half][h * 2 + 0];
                    float v1 = acc[mt][bt][half][h * 2 + 1];
                    float2 b2 = *(const float2*)(bias + col);
                    float2 c2 = *(const float2*)(curRow + col);
                    if (MODE == 0) {
                        float2 t2 = *(const float2*)(td + col);
                        float s0 = (1.f / (1.f + expf(-(v0 + b2.x)))) * c2.x * t2.x;
                        float s1 = (1.f / (1.f + expf(-(v1 + b2.y)))) * c2.y * t2.y;
                        uint32_t hi, lo;
                        split2(s0, s1, hi, lo);
                        *(uint32_t*)(outHi + grow * DIM + col) = hi;
                        *(uint32_t*)(outLo + grow * DIM + col) = lo;
                    } else {
                        float2 o;
                        o.x = v0 + b2.x + c2.x;
                        o.y = v1 + b2.y + c2.y;
                        *(float2*)(outF + grow * DIM + col) = o;
                    }
                }
            }
        }
    }
}

// ---------------- LayerNorm, both stacks batched; optional split output ----------------
__global__ __launch_bounds__(256)
void ln_kernel(const float* __restrict__ Y,
               const float* __restrict__ gE, const float* __restrict__ betaE,
               const float* __restrict__ gT, const float* __restrict__ betaT,
               float* __restrict__ outE, float* __restrict__ outT,
               __nv_bfloat16* __restrict__ outHi, __nv_bfloat16* __restrict__ outLo)
{
    const size_t row = blockIdx.x;                 // 0..2T-1
    const int stk = (int)(row >> 14);              // T_TOK = 16384
    const size_t lrow = row & (T_TOK - 1);
    const int tid = threadIdx.x;
    float4 v = ((const float4*)(Y + row * DIM))[tid];

    float s = v.x + v.y + v.z + v.w;
    float q = fmaf(v.x, v.x, fmaf(v.y, v.y, fmaf(v.z, v.z, v.w * v.w)));
#pragma unroll
    for (int off = 16; off; off >>= 1) {
        s += __shfl_xor_sync(0xffffffffu, s, off);
        q += __shfl_xor_sync(0xffffffffu, q, off);
    }
    __shared__ float ss[8], qq[8], mv[2];
    if ((tid & 31) == 0) { ss[tid >> 5] = s; qq[tid >> 5] = q; }
    __syncthreads();
    if (tid == 0) {
        float S = 0.f, Q = 0.f;
#pragma unroll
        for (int w = 0; w < 8; ++w) { S += ss[w]; Q += qq[w]; }
        float mean = S * (1.0f / DIM);
        float var  = Q * (1.0f / DIM) - mean * mean;
        mv[0] = mean;
        mv[1] = rsqrtf(var + LN_EPS);
    }
    __syncthreads();
    const float mean = mv[0], rstd = mv[1];
    const float* g    = stk ? gT    : gE;
    const float* beta = stk ? betaT : betaE;
    float4 g4 = ((const float4*)g)[tid];
    float4 b4 = ((const float4*)beta)[tid];
    float4 o;
    o.x = (v.x - mean) * rstd * g4.x + b4.x;
    o.y = (v.y - mean) * rstd * g4.y + b4.y;
    o.z = (v.z - mean) * rstd * g4.z + b4.z;
    o.w = (v.w - mean) * rstd * g4.w + b4.w;
    float* out = stk ? outT : outE;
    ((float4*)(out + lrow * DIM))[tid] = o;
    if (outHi) {
        unsigned long long hi, lo;
        split4(o, hi, lo);
        ((unsigned long long*)(outHi + row * DIM))[tid] = hi;
        ((unsigned long long*)(outLo + row * DIM))[tid] = lo;
    }
}

// ---------------- MoLE ----------------
__device__ __forceinline__ float gelu_exact(float x)
{
    return 0.5f * x * (1.f + erff(x * 0.70710678118654752440f));
}

__global__ __launch_bounds__(128)
void mole_kernel(const float* __restrict__ Z, const float* __restrict__ gate_W,
                 const float* __restrict__ gate_b, const float* __restrict__ lora_A,
                 const float* __restrict__ lora_B, float* __restrict__ pred,
                 float* __restrict__ gp)
{
    const size_t t = blockIdx.x;
    const int tid = threadIdx.x;
    const int lane = tid & 31, wid = tid >> 5;

    __shared__ float xs[DIM];
    __shared__ float lred[4][4];
    __shared__ float hred[4][32];
    __shared__ float hs[32];
    __shared__ int   eidx[2];

    ((float4*)xs)[tid]       = ((const float4*)(Z + t * DIM))[tid];
    ((float4*)xs)[tid + 128] = ((const float4*)(Z + t * DIM))[tid + 128];
    __syncthreads();

    float4 la = {0.f, 0.f, 0.f, 0.f};
    for (int d = tid; d < DIM; d += 128) {
        float xv = xs[d];
        float4 w = *(const float4*)(gate_W + d * NEXP);
        la.x = fmaf(xv, w.x, la.x);
        la.y = fmaf(xv, w.y, la.y);
        la.z = fmaf(xv, w.z, la.z);
        la.w = fmaf(xv, w.w, la.w);
    }
#pragma unroll
    for (int off = 16; off; off >>= 1) {
        la.x += __shfl_xor_sync(0xffffffffu, la.x, off);
        la.y += __shfl_xor_sync(0xffffffffu, la.y, off);
        la.z += __shfl_xor_sync(0xffffffffu, la.z, off);
        la.w += __shfl_xor_sync(0xffffffffu, la.w, off);
    }
    if (lane == 0) {
        lred[wid][0] = la.x; lred[wid][1] = la.y;
        lred[wid][2] = la.z; lred[wid][3] = la.w;
    }
    __syncthreads();

    if (tid == 0) {
        float lg[NEXP];
#pragma unroll
        for (int e = 0; e < NEXP; ++e)
            lg[e] = lred[0][e] + lred[1][e] + lred[2][e] + lred[3][e] + gate_b[e];
        float m = lg[0];
#pragma unroll
        for (int e = 1; e < NEXP; ++e) m = fmaxf(m, lg[e]);
        float p[NEXP], s = 0.f;
#pragma unroll
        for (int e = 0; e < NEXP; ++e) { p[e] = expf(lg[e] - m); s += p[e]; }
        float inv = 1.f / s;
#pragma unroll
        for (int e = 0; e < NEXP; ++e) gp[t * NEXP + e] = p[e] * inv;
        int i0 = 0;
#pragma unroll
        for (int e = 1; e < NEXP; ++e) if (lg[e] > lg[i0]) i0 = e;
        int i1 = -1;
#pragma unroll
        for (int e = 0; e < NEXP; ++e)
            if (e != i0 && (i1 < 0 || lg[e] > lg[i1])) i1 = e;
        eidx[0] = i0; eidx[1] = i1;
    }
    __syncthreads();

    const int e0 = eidx[0], e1 = eidx[1];
    const float* A0 = lora_A + (size_t)e0 * DIM * RRANK;
    const float* A1 = lora_A + (size_t)e1 * DIM * RRANK;

    float hacc[32];
#pragma unroll
    for (int i = 0; i < 32; ++i) hacc[i] = 0.f;
    for (int d = tid; d < DIM; d += 128) {
        float xv = xs[d];
        const float4* a0 = (const float4*)(A0 + d * RRANK);
        const float4* a1 = (const float4*)(A1 + d * RRANK);
#pragma unroll
        for (int q = 0; q < 4; ++q) {
            float4 a = a0[q];
            hacc[q * 4 + 0] = fmaf(xv, a.x, hacc[q * 4 + 0]);
            hacc[q * 4 + 1] = fmaf(xv, a.y, hacc[q * 4 + 1]);
            hacc[q * 4 + 2] = fmaf(xv, a.z, hacc[q * 4 + 2]);
            hacc[q * 4 + 3] = fmaf(xv, a.w, hacc[q * 4 + 3]);
        }
#pragma unroll
        for (int q = 0; q < 4; ++q) {
            float4 a = a1[q];
            hacc[16 + q * 4 + 0] = fmaf(xv, a.x, hacc[16 + q * 4 + 0]);
            hacc[16 + q * 4 + 1] = fmaf(xv, a.y, hacc[16 + q * 4 + 1]);
            hacc[16 + q * 4 + 2] = fmaf(xv, a.z, hacc[16 + q * 4 + 2]);
            hacc[16 + q * 4 + 3] = fmaf(xv, a.w, hacc[16 + q * 4 + 3]);
        }
    }
#pragma unroll
    for (int off = 16; off; off >>= 1)
#pragma unroll
        for (int i = 0; i < 32; ++i)
            hacc[i] += __shfl_xor_sync(0xffffffffu, hacc[i], off);
    if (lane == 0)
#pragma unroll
        for (int i = 0; i < 32; ++i) hred[wid][i] = hacc[i];
    __syncthreads();
    if (tid < 32) {
        float v = hred[0][tid] + hred[1][tid] + hred[2][tid] + hred[3][tid];
        hs[tid] = gelu_exact(v);
    }
    __syncthreads();

    const float* B0 = lora_B + (size_t)e0 * RRANK * DIM;
    const float* B1 = lora_B + (size_t)e1 * RRANK * DIM;
#pragma unroll
    for (int i = 0; i < 8; ++i) {
        const int d = tid + i * 128;
        float acc = 0.f;
#pragma unroll
        for (int r = 0; r < RRANK; ++r) {
            acc = fmaf(hs[r],      B0[r * DIM + d], acc);
            acc = fmaf(hs[16 + r], B1[r * DIM + d], acc);
        }
        pred[t * DIM + d] = acc;
    }
}

// ---------------- host orchestration ----------------
extern "C" void kernel_launch(void* const* d_in, const int* in_sizes, int n_in,
                              void* d_out, int out_size)
{
    const float* x_context = (const float*)d_in[0];
    const float* x_target  = (const float*)d_in[1];
    const float* enc_Wi   = (const float*)d_in[2];
    const float* enc_bi   = (const float*)d_in[3];
    const float* enc_td   = (const float*)d_in[4];
    const float* enc_Wo   = (const float*)d_in[5];
    const float* enc_bo   = (const float*)d_in[6];
    const float* enc_g    = (const float*)d_in[7];
    const float* enc_beta = (const float*)d_in[8];
    const float* tgt_Wi   = (const float*)d_in[9];
    const float* tgt_bi   = (const float*)d_in[10];
    const float* tgt_td   = (const float*)d_in[11];
    const float* tgt_Wo   = (const float*)d_in[12];
    const float* tgt_bo   = (const float*)d_in[13];
    const float* tgt_g    = (const float*)d_in[14];
    const float* tgt_beta = (const float*)d_in[15];
    const float* gate_W   = (const float*)d_in[16];
    const float* gate_b   = (const float*)d_in[17];
    const float* lora_A   = (const float*)d_in[18];
    const float* lora_B   = (const float*)d_in[19];

    float *bufY, *bufA;
    __nv_bfloat16 *zhi, *zlo, *shi, *slo, *whiAll, *wloAll;
    cudaGetSymbolAddress((void**)&bufY, g_bufY);
    cudaGetSymbolAddress((void**)&bufA, g_bufA);
    cudaGetSymbolAddress((void**)&zhi, g_Zhi);
    cudaGetSymbolAddress((void**)&zlo, g_Zlo);
    cudaGetSymbolAddress((void**)&shi, g_Shi);
    cudaGetSymbolAddress((void**)&slo, g_Slo);
    cudaGetSymbolAddress((void**)&whiAll, g_WhiAll);
    cudaGetSymbolAddress((void**)&wloAll, g_WloAll);

    cudaFuncSetAttribute(gemm_mma<0>, cudaFuncAttributeMaxDynamicSharedMemorySize, SMEMSZ);
    cudaFuncSetAttribute(gemm_mma<1>, cudaFuncAttributeMaxDynamicSharedMemorySize, SMEMSZ);

    float* out  = (float*)d_out;
    float* pred = out;                                   // [T, D]
    float* gp   = out + (size_t)T_TOK * DIM;             // [T, E]
    float* ztg  = gp + (size_t)T_TOK * NEXP;             // [T, D]

    // all weight splits upfront, one launch
    wsplit_all_kernel<<<dim3(DIM / 32, DIM / 32, 12), 256>>>(
        enc_Wi, enc_Wo, tgt_Wi, tgt_Wo, whiAll, wloAll);
    // split both stack inputs, one launch
    xsplit_kernel<<<dim3((T_TOK * DIM / 4) / 256, 2), 256>>>(x_context, x_target, zhi, zlo);

    dim3 ggrid(DIM / 128, T_TOK / 128, 2);
    const float* curE = x_context;
    const float* curT = x_target;
    for (int l = 0; l < NL; ++l) {
        gemm_mma<0><<<ggrid, 128, SMEMSZ>>>(
            zhi, zlo, whiAll, wloAll, l * 2 + 0,
            enc_bi + l * DIM, tgt_bi + l * DIM, curE, curT,
            enc_td + l * DIM, tgt_td + l * DIM, nullptr, shi, slo);
        gemm_mma<1><<<ggrid, 128, SMEMSZ>>>(
            shi, slo, whiAll, wloAll, l * 2 + 1,
            enc_bo + l * DIM, tgt_bo + l * DIM, curE, curT,
            nullptr, nullptr, bufY, nullptr, nullptr);
        const bool last = (l == NL - 1);
        ln_kernel<<<T2, 256>>>(bufY,
                               enc_g + l * DIM, enc_beta + l * DIM,
                               tgt_g + l * DIM, tgt_beta + l * DIM,
                               bufA, last ? ztg : (bufA + (size_t)T_TOK * DIM),
                               last ? nullptr : zhi, last ? nullptr : zlo);
        curE = bufA;
        curT = bufA + (size_t)T_TOK * DIM;
    }

    // MoLE on z_context (enc half of bufA) -> pred_z + gate_probs
    mole_kernel<<<T_TOK, 128>>>(bufA, gate_W, gate_b, lora_A, lora_B, pred, gp);
}

// round 17
// speedup vs baseline: 1.0733x; 1.0733x over previous
#include <cuda_runtime.h>
#include <cuda_bf16.h>
#include <math.h>
#include <stdint.h>

#define DIM   1024
#define T_TOK 16384
#define NL    3
#define NEXP  4
#define RRANK 16
#define LN_EPS 1e-5f

#define T2 (2 * T_TOK)     // both stacks batched

// ---------------- scratch (no allocations allowed) ----------------
__device__ float g_bufY[(size_t)T2 * DIM];               // pre-LN Y (fp32), batched
__device__ float g_bufA[(size_t)T2 * DIM];               // post-LN activation, batched
__device__ __nv_bfloat16 g_Zhi[(size_t)T2 * DIM];        // gemm0 A operand split
__device__ __nv_bfloat16 g_Zlo[(size_t)T2 * DIM];
__device__ __nv_bfloat16 g_Shi[(size_t)T2 * DIM];        // liquid state S split
__device__ __nv_bfloat16 g_Slo[(size_t)T2 * DIM];
// 12 weight slots: slot = stk*6 + l*2 + which(0=Wi,1=Wo); each W^T [N][K]
__device__ __nv_bfloat16 g_WhiAll[(size_t)12 * DIM * DIM];
__device__ __nv_bfloat16 g_WloAll[(size_t)12 * DIM * DIM];

// ================= PTX helpers (base compute_103 only) =================
__device__ __forceinline__ uint32_t smem_u32(const void* p) {
    uint32_t a;
    asm("{ .reg .u64 t; cvta.to.shared.u64 t, %1; cvt.u32.u64 %0, t; }" : "=r"(a) : "l"(p));
    return a;
}

__device__ __forceinline__ void cp_async16(uint32_t dst, const void* src) {
    asm volatile("cp.async.cg.shared.global [%0], [%1], 16;" :: "r"(dst), "l"(src));
}
#define CP_COMMIT() asm volatile("cp.async.commit_group;" ::: "memory")
#define CP_WAIT0()  asm volatile("cp.async.wait_group 0;" ::: "memory")
#define CP_WAIT1()  asm volatile("cp.async.wait_group 1;" ::: "memory")

__device__ __forceinline__ void ldsm_x4(uint32_t* r, uint32_t addr) {
    asm volatile("ldmatrix.sync.aligned.m8n8.x4.shared.b16 {%0,%1,%2,%3}, [%4];"
                 : "=r"(r[0]), "=r"(r[1]), "=r"(r[2]), "=r"(r[3]) : "r"(addr));
}

__device__ __forceinline__ void mma_bf16(float* d, const uint32_t* a, const uint32_t* b) {
    asm volatile(
        "mma.sync.aligned.m16n8k16.row.col.f32.bf16.bf16.f32 "
        "{%0,%1,%2,%3}, {%4,%5,%6,%7}, {%8,%9}, {%0,%1,%2,%3};"
        : "+f"(d[0]), "+f"(d[1]), "+f"(d[2]), "+f"(d[3])
        : "r"(a[0]), "r"(a[1]), "r"(a[2]), "r"(a[3]), "r"(b[0]), "r"(b[1]));
}

// split a float4 into packed-4 hi bf16 and packed-4 lo bf16 (8 bytes each)
__device__ __forceinline__ void split4(float4 v, unsigned long long& hi, unsigned long long& lo) {
    __nv_bfloat162 h0 = __float22bfloat162_rn(make_float2(v.x, v.y));
    __nv_bfloat162 h1 = __float22bfloat162_rn(make_float2(v.z, v.w));
    float2 f0 = __bfloat1622float2(h0);
    float2 f1 = __bfloat1622float2(h1);
    __nv_bfloat162 l0 = __float22bfloat162_rn(make_float2(v.x - f0.x, v.y - f0.y));
    __nv_bfloat162 l1 = __float22bfloat162_rn(make_float2(v.z - f1.x, v.w - f1.y));
    uint32_t uh0 = *reinterpret_cast<uint32_t*>(&h0);
    uint32_t uh1 = *reinterpret_cast<uint32_t*>(&h1);
    uint32_t ul0 = *reinterpret_cast<uint32_t*>(&l0);
    uint32_t ul1 = *reinterpret_cast<uint32_t*>(&l1);
    hi = (unsigned long long)uh0 | ((unsigned long long)uh1 << 32);
    lo = (unsigned long long)ul0 | ((unsigned long long)ul1 << 32);
}

__device__ __forceinline__ void split2(float a, float b, uint32_t& hi, uint32_t& lo) {
    __nv_bfloat162 h = __float22bfloat162_rn(make_float2(a, b));
    float2 f = __bfloat1622float2(h);
    __nv_bfloat162 l = __float22bfloat162_rn(make_float2(a - f.x, b - f.y));
    hi = *reinterpret_cast<uint32_t*>(&h);
    lo = *reinterpret_cast<uint32_t*>(&l);
}

// ---------------- x split: both stacks in one launch (z = stack) ----------------
__global__ __launch_bounds__(256)
void xsplit_kernel(const float* __restrict__ XE, const float* __restrict__ XT,
                   __nv_bfloat16* __restrict__ Xhi, __nv_bfloat16* __restrict__ Xlo)
{
    const int stk = blockIdx.y;
    const float* X = stk ? XT : XE;
    const size_t idx = (size_t)blockIdx.x * 256 + threadIdx.x;               // float4 idx
    const size_t gout = (size_t)stk * (T_TOK * DIM / 4) + idx;
    float4 v = ((const float4*)X)[idx];
    unsigned long long hi, lo;
    split4(v, hi, lo);
    ((unsigned long long*)Xhi)[gout] = hi;
    ((unsigned long long*)Xlo)[gout] = lo;
}

// ---------------- all 12 weight transpose+splits in ONE launch ----------------
__global__ __launch_bounds__(256)
void wsplit_all_kernel(const float* __restrict__ encWi, const float* __restrict__ encWo,
                       const float* __restrict__ tgtWi, const float* __restrict__ tgtWo,
                       __nv_bfloat16* __restrict__ WhiAll, __nv_bfloat16* __restrict__ WloAll)
{
    __shared__ float tile[32][33];
    const int s = blockIdx.z;
    const int stk = s / 6, rem = s % 6, l = rem >> 1, which = rem & 1;
    const float* Wbase = stk ? (which ? tgtWo : tgtWi) : (which ? encWo : encWi);
    const float* W = Wbase + (size_t)l * DIM * DIM;
    __nv_bfloat16* Whi = WhiAll + (size_t)s * DIM * DIM;
    __nv_bfloat16* Wlo = WloAll + (size_t)s * DIM * DIM;

    const int n0 = blockIdx.x * 32, k0 = blockIdx.y * 32;
    const int tx = threadIdx.x & 31, ty = threadIdx.x >> 5;
#pragma unroll
    for (int i = 0; i < 32; i += 8)
        tile[ty + i][tx] = W[(size_t)(k0 + ty + i) * DIM + n0 + tx];
    __syncthreads();
#pragma unroll
    for (int i = 0; i < 32; i += 8) {
        float v = tile[tx][ty + i];             // W[k0+tx][n0+ty+i]
        __nv_bfloat16 h = __float2bfloat16(v);
        const size_t o = (size_t)(n0 + ty + i) * DIM + k0 + tx;
        Whi[o] = h;
        Wlo[o] = __float2bfloat16(v - __bfloat162float(h));
    }
}

// shared constants for both GEMM geometries
#define BKC      32
#define NCH      (DIM / BKC)     // 32
#define STAGE_B  32768
#define NSTAGE   3
#define SMEMSZ   (NSTAGE * STAGE_B)
// stage (32KB): Ah[128][32] @0, Al @8192, Bh[128n][32k] @16384, Bl @24576
// layout: byteoff(row, q16B) = row*64 + ((q ^ (row&3))<<4)

// ---------------- GEMM 0 (liquid gate): 8 warps, 64x32 warp tiles ----------------
// s = sigmoid(acc + bias[c]) * cur[r,c] * td[c]  -> split bf16 (outHi/outLo, batched)
__global__ __launch_bounds__(256, 2)
void gemm_mma0(const __nv_bfloat16* __restrict__ Ahi, const __nv_bfloat16* __restrict__ Alo,
               const __nv_bfloat16* __restrict__ WhiAll, const __nv_bfloat16* __restrict__ WloAll,
               int wslot,
               const float* __restrict__ biasE, const float* __restrict__ biasT,
               const float* __restrict__ curE, const float* __restrict__ curT,
               const float* __restrict__ tdE, const float* __restrict__ tdT,
               __nv_bfloat16* __restrict__ outHi, __nv_bfloat16* __restrict__ outLo)
{
    extern __shared__ char smem[];
    const uint32_t sb = smem_u32(smem);
    const int tid  = threadIdx.x;
    const int wid  = tid >> 5, lane = tid & 31;
    const int mTile = blockIdx.y, nTile = blockIdx.x;
    const int stk = blockIdx.z;
    const int wm = wid >> 2;      // 0..1
    const int wn = wid & 3;       // 0..3

    const size_t rowBaseG = (size_t)stk * T_TOK + (size_t)mTile * 128;
    const __nv_bfloat16* AhG = Ahi + rowBaseG * DIM;
    const __nv_bfloat16* AlG = Alo + rowBaseG * DIM;
    const size_t wOff = ((size_t)(wslot + stk * 6)) * DIM * DIM + (size_t)nTile * 128 * DIM;
    const __nv_bfloat16* BhG = WhiAll + wOff;
    const __nv_bfloat16* BlG = WloAll + wOff;

    const float* bias = stk ? biasT : biasE;
    const float* cur  = stk ? curT  : curE;     // indexed by LOCAL row
    const float* td   = stk ? tdT   : tdE;

    const int fR = tid >> 2;      // 0..63
    const int fQ = tid & 3;       // 16B chunk within 64B row

    float acc[4][4][4];
#pragma unroll
    for (int mt = 0; mt < 4; ++mt)
#pragma unroll
        for (int nt = 0; nt < 4; ++nt)
#pragma unroll
            for (int r = 0; r < 4; ++r) acc[mt][nt][r] = 0.f;

    auto fillStage = [&](int st, int k0) {
        const uint32_t base = sb + st * STAGE_B;
#pragma unroll
        for (int i = 0; i < 2; ++i) {
            const int r = fR + i * 64;
            const uint32_t off = (uint32_t)(r * 64 + ((fQ ^ (r & 3)) << 4));
            const size_t go = (size_t)r * DIM + k0 + fQ * 8;
            cp_async16(base + off,         AhG + go);
            cp_async16(base + 8192 + off,  AlG + go);
            cp_async16(base + 16384 + off, BhG + go);
            cp_async16(base + 24576 + off, BlG + go);
        }
        CP_COMMIT();
    };

    fillStage(0, 0);
    fillStage(1, BKC);

    const int l7 = lane & 7, l8 = (lane >> 3) & 1, l16 = lane >> 4;

    for (int c = 0; c < NCH; ++c) {
        if (c + 1 < NCH) { CP_WAIT1(); } else { CP_WAIT0(); }
        __syncthreads();
        if (c + 2 < NCH) fillStage((c + 2) % NSTAGE, (c + 2) * BKC);

        const uint32_t sA = sb + (c % NSTAGE) * STAGE_B;
        const uint32_t sB = sA + 16384;
#pragma unroll
        for (int ks = 0; ks < 2; ++ks) {
            uint32_t b_hi[2][4], b_lo[2][4];
#pragma unroll
            for (int bt = 0; bt < 2; ++bt) {
                const int n = wn * 32 + bt * 16 + l16 * 8 + l7;
                const int ch = (ks * 2 + l8) ^ (n & 3);
                const uint32_t off = (uint32_t)(n * 64 + (ch << 4));
                ldsm_x4(b_hi[bt], sB + off);
                ldsm_x4(b_lo[bt], sB + 8192 + off);
            }
#pragma unroll
            for (int mt = 0; mt < 4; ++mt) {
                uint32_t a_hi[4], a_lo[4];
                const int r = wm * 64 + mt * 16 + l8 * 8 + l7;
                const int ch = (ks * 2 + l16) ^ (r & 3);
                const uint32_t off = (uint32_t)(r * 64 + (ch << 4));
                ldsm_x4(a_hi, sA + off);
                ldsm_x4(a_lo, sA + 8192 + off);
#pragma unroll
                for (int bt = 0; bt < 2; ++bt) {
                    mma_bf16(acc[mt][bt * 2 + 0], a_hi, &b_hi[bt][0]);
                    mma_bf16(acc[mt][bt * 2 + 0], a_hi, &b_lo[bt][0]);
                    mma_bf16(acc[mt][bt * 2 + 0], a_lo, &b_hi[bt][0]);
                    mma_bf16(acc[mt][bt * 2 + 1], a_hi, &b_hi[bt][2]);
                    mma_bf16(acc[mt][bt * 2 + 1], a_hi, &b_lo[bt][2]);
                    mma_bf16(acc[mt][bt * 2 + 1], a_lo, &b_hi[bt][2]);
                }
            }
        }
    }

    // ---- epilogue: sigmoid gate (fast exp), split-store ----
    const int rq = lane >> 2;
    const int cq = (lane & 3) * 2;
#pragma unroll
    for (int mt = 0; mt < 4; ++mt) {
#pragma unroll
        for (int h = 0; h < 2; ++h) {
            const int lrow = mTile * 128 + wm * 64 + mt * 16 + h * 8 + rq;
            const size_t grow = (size_t)stk * T_TOK + lrow;
            const float* curRow = cur + (size_t)lrow * DIM;
#pragma unroll
            for (int nt = 0; nt < 4; ++nt) {
                const int col = nTile * 128 + wn * 32 + nt * 8 + cq;
                float v0 = acc[mt][nt][h * 2 + 0];
                float v1 = acc[mt][nt][h * 2 + 1];
                float2 b2 = *(const float2*)(bias + col);
                float2 c2 = *(const float2*)(curRow + col);
                float2 t2 = *(const float2*)(td + col);
                float g0 = __fdividef(1.f, 1.f + __expf(-(v0 + b2.x)));
                float g1 = __fdividef(1.f, 1.f + __expf(-(v1 + b2.y)));
                float s0 = g0 * c2.x * t2.x;
                float s1 = g1 * c2.y * t2.y;
                uint32_t hi, lo;
                split2(s0, s1, hi, lo);
                *(uint32_t*)(outHi + grow * DIM + col) = hi;
                *(uint32_t*)(outLo + grow * DIM + col) = lo;
            }
        }
    }
}

// ---------------- GEMM 1 (proj + residual): 4 warps, 64x64 warp tiles ----------------
// out = acc + bias[c] + cur[r,c]  -> fp32 (outF, batched)
__global__ __launch_bounds__(128, 2)
void gemm_mma1(const __nv_bfloat16* __restrict__ Ahi, const __nv_bfloat16* __restrict__ Alo,
               const __nv_bfloat16* __restrict__ WhiAll, const __nv_bfloat16* __restrict__ WloAll,
               int wslot,
               const float* __restrict__ biasE, const float* __restrict__ biasT,
               const float* __restrict__ curE, const float* __restrict__ curT,
               float* __restrict__ outF)
{
    extern __shared__ char smem[];
    const uint32_t sb = smem_u32(smem);
    const int tid  = threadIdx.x;
    const int wid  = tid >> 5, lane = tid & 31;
    const int mTile = blockIdx.y, nTile = blockIdx.x;
    const int stk = blockIdx.z;
    const int wm = wid >> 1;      // 0..1
    const int wn = wid & 1;       // 0..1

    const size_t rowBaseG = (size_t)stk * T_TOK + (size_t)mTile * 128;
    const __nv_bfloat16* AhG = Ahi + rowBaseG * DIM;
    const __nv_bfloat16* AlG = Alo + rowBaseG * DIM;
    const size_t wOff = ((size_t)(wslot + stk * 6)) * DIM * DIM + (size_t)nTile * 128 * DIM;
    const __nv_bfloat16* BhG = WhiAll + wOff;
    const __nv_bfloat16* BlG = WloAll + wOff;

    const float* bias = stk ? biasT : biasE;
    const float* cur  = stk ? curT  : curE;     // indexed by LOCAL row

    const int fR = tid >> 2;      // 0..31
    const int fQ = tid & 3;       // 16B chunk within 64B row

    float acc[4][4][2][4];
#pragma unroll
    for (int mt = 0; mt < 4; ++mt)
#pragma unroll
        for (int bt = 0; bt < 4; ++bt)
#pragma unroll
            for (int h = 0; h < 2; ++h)
#pragma unroll
                for (int r = 0; r < 4; ++r) acc[mt][bt][h][r] = 0.f;

    auto fillStage = [&](int st, int k0) {
        const uint32_t base = sb + st * STAGE_B;
#pragma unroll
        for (int i = 0; i < 4; ++i) {
            const int r = fR + i * 32;
            const uint32_t off = (uint32_t)(r * 64 + ((fQ ^ (r & 3)) << 4));
            const size_t go = (size_t)r * DIM + k0 + fQ * 8;
            cp_async16(base + off,         AhG + go);
            cp_async16(base + 8192 + off,  AlG + go);
            cp_async16(base + 16384 + off, BhG + go);
            cp_async16(base + 24576 + off, BlG + go);
        }
        CP_COMMIT();
    };

    fillStage(0, 0);
    fillStage(1, BKC);

    const int l7 = lane & 7, l8 = (lane >> 3) & 1, l16 = lane >> 4;

    for (int c = 0; c < NCH; ++c) {
        if (c + 1 < NCH) { CP_WAIT1(); } else { CP_WAIT0(); }
        __syncthreads();
        if (c + 2 < NCH) fillStage((c + 2) % NSTAGE, (c + 2) * BKC);

        const uint32_t sA = sb + (c % NSTAGE) * STAGE_B;
        const uint32_t sB = sA + 16384;
#pragma unroll
        for (int ks = 0; ks < 2; ++ks) {
            uint32_t b_hi[4][4], b_lo[4][4];
#pragma unroll
            for (int bt = 0; bt < 4; ++bt) {
                const int n = wn * 64 + bt * 16 + l16 * 8 + l7;
                const int ch = (ks * 2 + l8) ^ (n & 3);
                const uint32_t off = (uint32_t)(n * 64 + (ch << 4));
                ldsm_x4(b_hi[bt], sB + off);
                ldsm_x4(b_lo[bt], sB + 8192 + off);
            }
#pragma unroll
            for (int mt = 0; mt < 4; ++mt) {
                uint32_t a_hi[4], a_lo[4];
                const int r = wm * 64 + mt * 16 + l8 * 8 + l7;
                const int ch = (ks * 2 + l16) ^ (r & 3);
                const uint32_t off = (uint32_t)(r * 64 + (ch << 4));
                ldsm_x4(a_hi, sA + off);
                ldsm_x4(a_lo, sA + 8192 + off);
#pragma unroll
                for (int bt = 0; bt < 4; ++bt) {
                    mma_bf16(acc[mt][bt][0], a_hi, &b_hi[bt][0]);
                    mma_bf16(acc[mt][bt][0], a_hi, &b_lo[bt][0]);
                    mma_bf16(acc[mt][bt][0], a_lo, &b_hi[bt][0]);
                    mma_bf16(acc[mt][bt][1], a_hi, &b_hi[bt][2]);
                    mma_bf16(acc[mt][bt][1], a_hi, &b_lo[bt][2]);
                    mma_bf16(acc[mt][bt][1], a_lo, &b_hi[bt][2]);
                }
            }
        }
    }

    // ---- epilogue: bias + residual, fp32 store ----
    const int rq = lane >> 2;
    const int cq = (lane & 3) * 2;
#pragma unroll
    for (int mt = 0; mt < 4; ++mt) {
#pragma unroll
        for (int h = 0; h < 2; ++h) {
            const int lrow = mTile * 128 + wm * 64 + mt * 16 + h * 8 + rq;
            const size_t grow = (size_t)stk * T_TOK + lrow;
            const float* curRow = cur + (size_t)lrow * DIM;
#pragma unroll
            for (int bt = 0; bt < 4; ++bt) {
#pragma unroll
                for (int half = 0; half < 2; ++half) {
                    const int col = nTile * 128 + wn * 64 + bt * 16 + half * 8 + cq;
                    float v0 = acc[mt][bt][half][h * 2 + 0];
                    float v1 = acc[mt][bt][half][h * 2 + 1];
                    float2 b2 = *(const float2*)(bias + col);
                    float2 c2 = *(const float2*)(curRow + col);
                    float2 o;
                    o.x = v0 + b2.x + c2.x;
                    o.y = v1 + b2.y + c2.y;
                    *(float2*)(outF + grow * DIM + col) = o;
                }
            }
        }
    }
}

// ---------------- LayerNorm, both stacks batched; optional split output ----------------
__global__ __launch_bounds__(256)
void ln_kernel(const float* __restrict__ Y,
               const float* __restrict__ gE, const float* __restrict__ betaE,
               const float* __restrict__ gT, const float* __restrict__ betaT,
               float* __restrict__ outE, float* __restrict__ outT,
               __nv_bfloat16* __restrict__ outHi, __nv_bfloat16* __restrict__ outLo)
{
    const size_t row = blockIdx.x;                 // 0..2T-1
    const int stk = (int)(row >> 14);              // T_TOK = 16384
    const size_t lrow = row & (T_TOK - 1);
    const int tid = threadIdx.x;
    float4 v = ((const float4*)(Y + row * DIM))[tid];

    float s = v.x + v.y + v.z + v.w;
    float q = fmaf(v.x, v.x, fmaf(v.y, v.y, fmaf(v.z, v.z, v.w * v.w)));
#pragma unroll
    for (int off = 16; off; off >>= 1) {
        s += __shfl_xor_sync(0xffffffffu, s, off);
        q += __shfl_xor_sync(0xffffffffu, q, off);
    }
    __shared__ float ss[8], qq[8], mv[2];
    if ((tid & 31) == 0) { ss[tid >> 5] = s; qq[tid >> 5] = q; }
    __syncthreads();
    if (tid == 0) {
        float S = 0.f, Q = 0.f;
#pragma unroll
        for (int w = 0; w < 8; ++w) { S += ss[w]; Q += qq[w]; }
        float mean = S * (1.0f / DIM);
        float var  = Q * (1.0f / DIM) - mean * mean;
        mv[0] = mean;
        mv[1] = rsqrtf(var + LN_EPS);
    }
    __syncthreads();
    const float mean = mv[0], rstd = mv[1];
    const float* g    = stk ? gT    : gE;
    const float* beta = stk ? betaT : betaE;
    float4 g4 = ((const float4*)g)[tid];
    float4 b4 = ((const float4*)beta)[tid];
    float4 o;
    o.x = (v.x - mean) * rstd * g4.x + b4.x;
    o.y = (v.y - mean) * rstd * g4.y + b4.y;
    o.z = (v.z - mean) * rstd * g4.z + b4.z;
    o.w = (v.w - mean) * rstd * g4.w + b4.w;
    float* out = stk ? outT : outE;
    ((float4*)(out + lrow * DIM))[tid] = o;
    if (outHi) {
        unsigned long long hi, lo;
        split4(o, hi, lo);
        ((unsigned long long*)(outHi + row * DIM))[tid] = hi;
        ((unsigned long long*)(outLo + row * DIM))[tid] = lo;
    }
}

// ---------------- MoLE ----------------
__device__ __forceinline__ float gelu_exact(float x)
{
    return 0.5f * x * (1.f + erff(x * 0.70710678118654752440f));
}

__global__ __launch_bounds__(128)
void mole_kernel(const float* __restrict__ Z, const float* __restrict__ gate_W,
                 const float* __restrict__ gate_b, const float* __restrict__ lora_A,
                 const float* __restrict__ lora_B, float* __restrict__ pred,
                 float* __restrict__ gp)
{
    const size_t t = blockIdx.x;
    const int tid = threadIdx.x;
    const int lane = tid & 31, wid = tid >> 5;

    __shared__ float xs[DIM];
    __shared__ float lred[4][4];
    __shared__ float hred[4][32];
    __shared__ float hs[32];
    __shared__ int   eidx[2];

    ((float4*)xs)[tid]       = ((const float4*)(Z + t * DIM))[tid];
    ((float4*)xs)[tid + 128] = ((const float4*)(Z + t * DIM))[tid + 128];
    __syncthreads();

    float4 la = {0.f, 0.f, 0.f, 0.f};
    for (int d = tid; d < DIM; d += 128) {
        float xv = xs[d];
        float4 w = *(const float4*)(gate_W + d * NEXP);
        la.x = fmaf(xv, w.x, la.x);
        la.y = fmaf(xv, w.y, la.y);
        la.z = fmaf(xv, w.z, la.z);
        la.w = fmaf(xv, w.w, la.w);
    }
#pragma unroll
    for (int off = 16; off; off >>= 1) {
        la.x += __shfl_xor_sync(0xffffffffu, la.x, off);
        la.y += __shfl_xor_sync(0xffffffffu, la.y, off);
        la.z += __shfl_xor_sync(0xffffffffu, la.z, off);
        la.w += __shfl_xor_sync(0xffffffffu, la.w, off);
    }
    if (lane == 0) {
        lred[wid][0] = la.x; lred[wid][1] = la.y;
        lred[wid][2] = la.z; lred[wid][3] = la.w;
    }
    __syncthreads();

    if (tid == 0) {
        float lg[NEXP];
#pragma unroll
        for (int e = 0; e < NEXP; ++e)
            lg[e] = lred[0][e] + lred[1][e] + lred[2][e] + lred[3][e] + gate_b[e];
        float m = lg[0];
#pragma unroll
        for (int e = 1; e < NEXP; ++e) m = fmaxf(m, lg[e]);
        float p[NEXP], s = 0.f;
#pragma unroll
        for (int e = 0; e < NEXP; ++e) { p[e] = expf(lg[e] - m); s += p[e]; }
        float inv = 1.f / s;
#pragma unroll
        for (int e = 0; e < NEXP; ++e) gp[t * NEXP + e] = p[e] * inv;
        int i0 = 0;
#pragma unroll
        for (int e = 1; e < NEXP; ++e) if (lg[e] > lg[i0]) i0 = e;
        int i1 = -1;
#pragma unroll
        for (int e = 0; e < NEXP; ++e)
            if (e != i0 && (i1 < 0 || lg[e] > lg[i1])) i1 = e;
        eidx[0] = i0; eidx[1] = i1;
    }
    __syncthreads();

    const int e0 = eidx[0], e1 = eidx[1];
    const float* A0 = lora_A + (size_t)e0 * DIM * RRANK;
    const float* A1 = lora_A + (size_t)e1 * DIM * RRANK;

    float hacc[32];
#pragma unroll
    for (int i = 0; i < 32; ++i) hacc[i] = 0.f;
    for (int d = tid; d < DIM; d += 128) {
        float xv = xs[d];
        const float4* a0 = (const float4*)(A0 + d * RRANK);
        const float4* a1 = (const float4*)(A1 + d * RRANK);
#pragma unroll
        for (int q = 0; q < 4; ++q) {
            float4 a = a0[q];
            hacc[q * 4 + 0] = fmaf(xv, a.x, hacc[q * 4 + 0]);
            hacc[q * 4 + 1] = fmaf(xv, a.y, hacc[q * 4 + 1]);
            hacc[q * 4 + 2] = fmaf(xv, a.z, hacc[q * 4 + 2]);
            hacc[q * 4 + 3] = fmaf(xv, a.w, hacc[q * 4 + 3]);
        }
#pragma unroll
        for (int q = 0; q < 4; ++q) {
            float4 a = a1[q];
            hacc[16 + q * 4 + 0] = fmaf(xv, a.x, hacc[16 + q * 4 + 0]);
            hacc[16 + q * 4 + 1] = fmaf(xv, a.y, hacc[16 + q * 4 + 1]);
            hacc[16 + q * 4 + 2] = fmaf(xv, a.z, hacc[16 + q * 4 + 2]);
            hacc[16 + q * 4 + 3] = fmaf(xv, a.w, hacc[16 + q * 4 + 3]);
        }
    }
#pragma unroll
    for (int off = 16; off; off >>= 1)
#pragma unroll
        for (int i = 0; i < 32; ++i)
            hacc[i] += __shfl_xor_sync(0xffffffffu, hacc[i], off);
    if (lane == 0)
#pragma unroll
        for (int i = 0; i < 32; ++i) hred[wid][i] = hacc[i];
    __syncthreads();
    if (tid < 32) {
        float v = hred[0][tid] + hred[1][tid] + hred[2][tid] + hred[3][tid];
        hs[tid] = gelu_exact(v);
    }
    __syncthreads();

    const float* B0 = lora_B + (size_t)e0 * RRANK * DIM;
    const float* B1 = lora_B + (size_t)e1 * RRANK * DIM;
#pragma unroll
    for (int i = 0; i < 8; ++i) {
        const int d = tid + i * 128;
        float acc = 0.f;
#pragma unroll
        for (int r = 0; r < RRANK; ++r) {
            acc = fmaf(hs[r],      B0[r * DIM + d], acc);
            acc = fmaf(hs[16 + r], B1[r * DIM + d], acc);
        }
        pred[t * DIM + d] = acc;
    }
}

// ---------------- host orchestration ----------------
extern "C" void kernel_launch(void* const* d_in, const int* in_sizes, int n_in,
                              void* d_out, int out_size)
{
    const float* x_context = (const float*)d_in[0];
    const float* x_target  = (const float*)d_in[1];
    const float* enc_Wi   = (const float*)d_in[2];
    const float* enc_bi   = (const float*)d_in[3];
    const float* enc_td   = (const float*)d_in[4];
    const float* enc_Wo   = (const float*)d_in[5];
    const float* enc_bo   = (const float*)d_in[6];
    const float* enc_g    = (const float*)d_in[7];
    const float* enc_beta = (const float*)d_in[8];
    const float* tgt_Wi   = (const float*)d_in[9];
    const float* tgt_bi   = (const float*)d_in[10];
    const float* tgt_td   = (const float*)d_in[11];
    const float* tgt_Wo   = (const float*)d_in[12];
    const float* tgt_bo   = (const float*)d_in[13];
    const float* tgt_g    = (const float*)d_in[14];
    const float* tgt_beta = (const float*)d_in[15];
    const float* gate_W   = (const float*)d_in[16];
    const float* gate_b   = (const float*)d_in[17];
    const float* lora_A   = (const float*)d_in[18];
    const float* lora_B   = (const float*)d_in[19];

    float *bufY, *bufA;
    __nv_bfloat16 *zhi, *zlo, *shi, *slo, *whiAll, *wloAll;
    cudaGetSymbolAddress((void**)&bufY, g_bufY);
    cudaGetSymbolAddress((void**)&bufA, g_bufA);
    cudaGetSymbolAddress((void**)&zhi, g_Zhi);
    cudaGetSymbolAddress((void**)&zlo, g_Zlo);
    cudaGetSymbolAddress((void**)&shi, g_Shi);
    cudaGetSymbolAddress((void**)&slo, g_Slo);
    cudaGetSymbolAddress((void**)&whiAll, g_WhiAll);
    cudaGetSymbolAddress((void**)&wloAll, g_WloAll);

    cudaFuncSetAttribute(gemm_mma0, cudaFuncAttributeMaxDynamicSharedMemorySize, SMEMSZ);
    cudaFuncSetAttribute(gemm_mma1, cudaFuncAttributeMaxDynamicSharedMemorySize, SMEMSZ);

    float* out  = (float*)d_out;
    float* pred = out;                                   // [T, D]
    float* gp   = out + (size_t)T_TOK * DIM;             // [T, E]
    float* ztg  = gp + (size_t)T_TOK * NEXP;             // [T, D]

    // all weight splits upfront, one launch
    wsplit_all_kernel<<<dim3(DIM / 32, DIM / 32, 12), 256>>>(
        enc_Wi, enc_Wo, tgt_Wi, tgt_Wo, whiAll, wloAll);
    // split both stack inputs, one launch
    xsplit_kernel<<<dim3((T_TOK * DIM / 4) / 256, 2), 256>>>(x_context, x_target, zhi, zlo);

    dim3 ggrid(DIM / 128, T_TOK / 128, 2);
    const float* curE = x_context;
    const float* curT = x_target;
    for (int l = 0; l < NL; ++l) {
        gemm_mma0<<<ggrid, 256, SMEMSZ>>>(
            zhi, zlo, whiAll, wloAll, l * 2 + 0,
            enc_bi + l * DIM, tgt_bi + l * DIM, curE, curT,
            enc_td + l * DIM, tgt_td + l * DIM, shi, slo);
        gemm_mma1<<<ggrid, 128, SMEMSZ>>>(
            shi, slo, whiAll, wloAll, l * 2 + 1,
            enc_bo + l * DIM, tgt_bo + l * DIM, curE, curT,
            bufY);
        const bool last = (l == NL - 1);
        ln_kernel<<<T2, 256>>>(bufY,
                               enc_g + l * DIM, enc_beta + l * DIM,
                               tgt_g + l * DIM, tgt_beta + l * DIM,
                               bufA, last ? ztg : (bufA + (size_t)T_TOK * DIM),
                               last ? nullptr : zhi, last ? nullptr : zlo);
        curE = bufA;
        curT = bufA + (size_t)T_TOK * DIM;
    }

    // MoLE on z_context (enc half of bufA) -> pred_z + gate_probs
    mole_kernel<<<T_TOK, 128>>>(bufA, gate_W, gate_b, lora_A, lora_B, pred, gp);
}